// round 2
// baseline (speedup 1.0000x reference)
#include <cuda_runtime.h>
#include <cstdint>

#define VV 49688
#define DD 128
#define BB 16
#define NN 100

// One thread per float4 of W; broadcast-store to all B output copies.
// W is 25.4 MB -> stays L2-resident across the 16 read passes.
__global__ void __launch_bounds__(256) bcast_copy_kernel(
    const float4* __restrict__ W4, float4* __restrict__ out4)
{
    const int nvec = VV * (DD / 4);               // 1,590,016 float4 per copy
    int j = blockIdx.x * blockDim.x + threadIdx.x;
    if (j >= nvec) return;
    float4 v = __ldg(&W4[j]);
    size_t base = (size_t)j;
#pragma unroll
    for (int b = 0; b < BB; ++b) {
        out4[base] = v;
        base += (size_t)nvec;
    }
}

// One block per (b, i) updated row; 32 threads x float4 = 128 floats.
// out[b, nodes[b,i], :] = (1-a)*W[node] + a*x[i]   (a = alpha[node])
__global__ void __launch_bounds__(32) blend_rows_kernel(
    const int* __restrict__ nodes,
    const float* __restrict__ x,
    const float* __restrict__ W,
    const float* __restrict__ alpha,
    float* __restrict__ out)
{
    int idx = blockIdx.x;            // 0 .. B*N-1
    int b = idx / NN;
    int i = idx - b * NN;            // x row index: reference uses x[:N] shared across batch
    int node = __ldg(&nodes[idx]);
    float a = __ldg(&alpha[node]);
    float oma = 1.0f - a;

    const float4* wrow = (const float4*)(W + (size_t)node * DD);
    const float4* xrow = (const float4*)(x + (size_t)i * DD);
    float4* orow = (float4*)(out + (size_t)b * VV * DD + (size_t)node * DD);

    int t = threadIdx.x;             // 0..31, 32 float4 = 128 floats
    float4 w = __ldg(&wrow[t]);
    float4 xv = __ldg(&xrow[t]);
    float4 r;
    r.x = oma * w.x + a * xv.x;
    r.y = oma * w.y + a * xv.y;
    r.z = oma * w.z + a * xv.z;
    r.w = oma * w.w + a * xv.w;
    orow[t] = r;
}

extern "C" void kernel_launch(void* const* d_in, const int* in_sizes, int n_in,
                              void* d_out, int out_size)
{
    const int*   nodes = (const int*)d_in[0];
    const float* x     = (const float*)d_in[1];
    const float* W     = (const float*)d_in[2];
    const float* alpha = (const float*)d_in[3];
    float*       out   = (float*)d_out;

    const int nvec = VV * (DD / 4);               // float4 count per batch copy
    int blocks = (nvec + 255) / 256;
    bcast_copy_kernel<<<blocks, 256>>>((const float4*)W, (float4*)out);
    blend_rows_kernel<<<BB * NN, 32>>>(nodes, x, W, alpha, out);
}

// round 3
// speedup vs baseline: 1.0857x; 1.0857x over previous
#include <cuda_runtime.h>
#include <cstdint>

#define VV 49688
#define DD 128
#define BB 16
#define NN 100

// One thread per float4 of W; broadcast-store to all B output copies.
// __ldg: W read path (25.4 MB, L2-resident across all 16 passes).
// __stcs: evict-first streaming stores so the 407 MB output stream does not
// evict W from L2 (output is never re-read by the GPU).
__global__ void __launch_bounds__(256) bcast_copy_kernel(
    const float4* __restrict__ W4, float4* __restrict__ out4)
{
    const int nvec = VV * (DD / 4);               // 1,590,016 float4 per copy
    int j = blockIdx.x * blockDim.x + threadIdx.x;
    if (j >= nvec) return;
    float4 v = __ldg(&W4[j]);
    size_t base = (size_t)j;
#pragma unroll
    for (int b = 0; b < BB; ++b) {
        __stcs(&out4[base], v);
        base += (size_t)nvec;
    }
}

// One thread per float4 of an updated row: B*N*32 = 51,200 threads (200 blocks).
// out[b, nodes[b,i], :] = (1-a)*W[node] + a*x[i]   (a = alpha[node]; x shared across batch)
__global__ void __launch_bounds__(256) blend_rows_kernel(
    const int* __restrict__ nodes,
    const float* __restrict__ x,
    const float* __restrict__ W,
    const float* __restrict__ alpha,
    float* __restrict__ out)
{
    int g = blockIdx.x * blockDim.x + threadIdx.x;
    if (g >= BB * NN * 32) return;
    int idx = g >> 5;                // row index 0 .. B*N-1
    int t   = g & 31;                // float4 lane within row
    int b = idx / NN;
    int i = idx - b * NN;
    int node = __ldg(&nodes[idx]);
    float a = __ldg(&alpha[node]);
    float oma = 1.0f - a;

    const float4* wrow = (const float4*)(W + (size_t)node * DD);
    const float4* xrow = (const float4*)(x + (size_t)i * DD);
    float4* orow = (float4*)(out + (size_t)b * VV * DD + (size_t)node * DD);

    float4 w = __ldg(&wrow[t]);
    float4 xv = __ldg(&xrow[t]);
    float4 r;
    r.x = oma * w.x + a * xv.x;
    r.y = oma * w.y + a * xv.y;
    r.z = oma * w.z + a * xv.z;
    r.w = oma * w.w + a * xv.w;
    __stcs(&orow[t], r);
}

extern "C" void kernel_launch(void* const* d_in, const int* in_sizes, int n_in,
                              void* d_out, int out_size)
{
    const int*   nodes = (const int*)d_in[0];
    const float* x     = (const float*)d_in[1];
    const float* W     = (const float*)d_in[2];
    const float* alpha = (const float*)d_in[3];
    float*       out   = (float*)d_out;

    const int nvec = VV * (DD / 4);               // float4 count per batch copy
    int blocks = (nvec + 255) / 256;
    bcast_copy_kernel<<<blocks, 256>>>((const float4*)W, (float4*)out);

    int bl_threads = BB * NN * 32;                // 51,200
    blend_rows_kernel<<<(bl_threads + 255) / 256, 256>>>(nodes, x, W, alpha, out);
}